// round 1
// baseline (speedup 1.0000x reference)
#include <cuda_runtime.h>

// QuantumRegression: 1024 x 14-qubit statevector sim, 3 layers (Rot per wire + CNOT ring),
// <Z_w> features, linear head.
//
// Design:
//  - 1 CTA per batch element; full state (16384 complex fp32 = 128KB) in dynamic SMEM.
//  - Rot gates fused in wire pairs -> 4x4 complex matvec (kron(U_w, U_{w+1})).
//    Wires 0..9: five in-place SMEM passes (insert positions >= 4 -> conflict-free LDS.64).
//    Wires 10..13: one register "tile" pass over 16 consecutive amps (float4 + lane rotation).
//  - CNOT ring = GF(2)-linear permutation P (prefix-xor). Materialized between layers via
//    whole-CTA register staging; final layer's P folded into measurement (o = P(j)).
//  - Complex MACs via packed fma.rn.f32x2 (2 instr per complex MAC).

#define NW   14
#define DIM  16384
#define NT   256

typedef unsigned long long u64;

__device__ float4 g_mats[21][16];   // per wire-pair 4x4: {ur, ur, -ui, ui}

// ---------------- setup: build fused 4x4 gate matrices ----------------

struct cpx { float re, im; };
__device__ __forceinline__ cpx cmul(cpx a, cpx b){
    cpx r; r.re = a.re*b.re - a.im*b.im; r.im = a.re*b.im + a.im*b.re; return r;
}

__device__ void rotmat(const float* p, cpx U[2][2]){
    float cx = cosf(0.5f*p[0]), sx = sinf(0.5f*p[0]);
    float cy = cosf(0.5f*p[1]), sy = sinf(0.5f*p[1]);
    float cz = cosf(0.5f*p[2]), sz = sinf(0.5f*p[2]);
    // RY @ RX
    cpx r00 = { cy*cx,  sy*sx};
    cpx r01 = {-sy*cx, -cy*sx};
    cpx r10 = { sy*cx, -cy*sx};
    cpx r11 = { cy*cx, -sy*sx};
    cpx e0 = {cz, -sz}, e1 = {cz, sz};   // RZ diagonal
    U[0][0] = cmul(e0, r00); U[0][1] = cmul(e0, r01);
    U[1][0] = cmul(e1, r10); U[1][1] = cmul(e1, r11);
}

__global__ void setup_mats(const float* __restrict__ vp){
    int pid = threadIdx.x;
    if (pid >= 21) return;
    int l = pid / 7, k = pid % 7;
    cpx Ua[2][2], Ub[2][2];
    rotmat(vp + (l*NW + 2*k    )*3, Ua);
    rotmat(vp + (l*NW + 2*k + 1)*3, Ub);
    #pragma unroll
    for (int i = 0; i < 2; i++)
    #pragma unroll
    for (int j = 0; j < 2; j++)
    #pragma unroll
    for (int a = 0; a < 2; a++)
    #pragma unroll
    for (int c = 0; c < 2; c++){
        cpx m = cmul(Ua[i][a], Ub[j][c]);        // kron: wire w more significant
        g_mats[pid][(2*i + j)*4 + (2*a + c)] = make_float4(m.re, m.re, -m.im, m.im);
    }
}

// ---------------- packed f32x2 helpers ----------------

__device__ __forceinline__ u64 pk2(float lo, float hi){
    u64 r; asm("mov.b64 %0, {%1,%2};" : "=l"(r) : "f"(lo), "f"(hi)); return r;
}
__device__ __forceinline__ void upk2(u64 v, float& lo, float& hi){
    asm("mov.b64 {%0,%1}, %2;" : "=f"(lo), "=f"(hi) : "l"(v));
}
__device__ __forceinline__ u64 swp2(u64 v){
    u64 r;
    asm("{ .reg .b32 a,b; mov.b64 {a,b}, %1; mov.b64 %0, {b,a}; }" : "=l"(r) : "l"(v));
    return r;
}
__device__ __forceinline__ u64 f2(u64 a, u64 b, u64 c){
    u64 r; asm("fma.rn.f32x2 %0, %1, %2, %3;" : "=l"(r) : "l"(a), "l"(b), "l"(c)); return r;
}
__device__ __forceinline__ u64 m2(u64 a, u64 b){
    u64 r; asm("mul.rn.f32x2 %0, %1, %2;" : "=l"(r) : "l"(a), "l"(b)); return r;
}

struct Mat4 { u64 u[16], n[16]; };

__device__ __forceinline__ void loadmat(Mat4& M, int pair){
    #pragma unroll
    for (int e = 0; e < 16; e++){
        float4 f = __ldg(&g_mats[pair][e]);
        M.u[e] = pk2(f.x, f.y);
        M.n[e] = pk2(f.z, f.w);
    }
}

// out_s = sum_t M[s,t] * in_t   (complex, packed (re,im))
__device__ __forceinline__ void mv4(const Mat4& M, const u64 v[4], const u64 vs[4], u64 o[4]){
    #pragma unroll
    for (int s = 0; s < 4; s++){
        u64 a = m2(M.u[4*s+0], v[0]);
        a = f2(M.n[4*s+0], vs[0], a);
        #pragma unroll
        for (int t = 1; t < 4; t++){
            a = f2(M.u[4*s+t], v[t], a);
            a = f2(M.n[4*s+t], vs[t], a);
        }
        o[s] = a;
    }
}

// ---------------- CNOT-ring permutation (GF2 linear) ----------------
// forward: o = P(i)
__device__ __forceinline__ int pfwd(int i){
    int y = i;
    y ^= y >> 1; y ^= y >> 2; y ^= y >> 4; y ^= y >> 8;   // suffix-xor
    return (y & 0x1FFF) ^ ((((y ^ (i >> 13)) & 1) << 13));
}
// inverse: i = P^{-1}(o)
__device__ __forceinline__ int pinv(int o){
    int t = o ^ (o >> 1);
    return (t & 0x1FFF) ^ (o & 0x2000) ^ ((o & 1) ? 0x3000 : 0);
}

// ---------------- passes ----------------

// two-wire in-place pass, insert position p (>= 4)
__device__ __forceinline__ void pass2w(float2* psi, const Mat4& M, int p, int t){
    const int lowmask = (1 << p) - 1;
    const int step = lowmask + 1;
    #pragma unroll 4
    for (int j = 0; j < 16; j++){
        int gid  = t + NT*j;                 // 0..4095
        int low  = gid & lowmask;
        int idx0 = ((gid ^ low) << 2) | low; // insert 2 bits at position p
        u64 v[4], vs[4], o[4];
        #pragma unroll
        for (int s = 0; s < 4; s++){
            float2 a = psi[idx0 + s*step];
            v[s]  = pk2(a.x, a.y);
            vs[s] = pk2(a.y, a.x);
        }
        mv4(M, v, vs, o);
        #pragma unroll
        for (int s = 0; s < 4; s++){
            float lo, hi; upk2(o[s], lo, hi);
            psi[idx0 + s*step] = make_float2(lo, hi);
        }
    }
}

// wires 10..13 (index bits 3..0): 16 consecutive amps per tile, two 4x4 stages in registers
__device__ __forceinline__ void tilepass(float2* psi, const Mat4& A, const Mat4& B, int t){
    float4* p4 = reinterpret_cast<float4*>(psi);
    const int rot = t & 7;
    #pragma unroll 1
    for (int tt = 0; tt < 4; tt++){
        int tile = t + NT*tt;                // 0..1023
        u64 amp[16];
        #pragma unroll
        for (int r = 0; r < 8; r++){
            int rr = (r + rot) & 7;
            float4 q = p4[tile*8 + rr];
            amp[2*rr]   = pk2(q.x, q.y);
            amp[2*rr+1] = pk2(q.z, q.w);
        }
        // stage A: wires 10,11 -> local bits (3,2)
        #pragma unroll
        for (int q = 0; q < 4; q++){
            u64 v[4], vs[4], o[4];
            #pragma unroll
            for (int s = 0; s < 4; s++){ v[s] = amp[(s<<2)|q]; vs[s] = swp2(v[s]); }
            mv4(A, v, vs, o);
            #pragma unroll
            for (int s = 0; s < 4; s++) amp[(s<<2)|q] = o[s];
        }
        // stage B: wires 12,13 -> local bits (1,0)
        #pragma unroll
        for (int q = 0; q < 4; q++){
            u64 v[4], vs[4], o[4];
            #pragma unroll
            for (int s = 0; s < 4; s++){ v[s] = amp[(q<<2)|s]; vs[s] = swp2(v[s]); }
            mv4(B, v, vs, o);
            #pragma unroll
            for (int s = 0; s < 4; s++) amp[(q<<2)|s] = o[s];
        }
        #pragma unroll
        for (int r = 0; r < 8; r++){
            int rr = (r + rot) & 7;
            float l0,h0,l1,h1;
            upk2(amp[2*rr],   l0, h0);
            upk2(amp[2*rr+1], l1, h1);
            p4[tile*8 + rr] = make_float4(l0, h0, l1, h1);
        }
    }
}

// materialize CNOT-ring permutation: whole-CTA register staging
__device__ __forceinline__ void permpass(float2* psi, int t){
    float2 tmp[64];
    #pragma unroll
    for (int j = 0; j < 64; j++){
        int o = t + NT*j;
        tmp[j] = psi[pinv(o)];
    }
    __syncthreads();
    #pragma unroll
    for (int j = 0; j < 64; j++)
        psi[t + NT*j] = tmp[j];
}

// ---------------- main kernel ----------------

__global__ void __launch_bounds__(NT, 1)
qsim_kernel(const float* __restrict__ sr, const float* __restrict__ si,
            const float* __restrict__ hw, const float* __restrict__ hb,
            float* __restrict__ out)
{
    extern __shared__ float2 psi[];
    const int t = threadIdx.x;
    const int b = blockIdx.x;

    // layer 0, pair 0 (wires 0,1 / position 12) fused with global load
    {
        Mat4 M; loadmat(M, 0);
        const float* srb = sr + (size_t)b * DIM;
        const float* sib = si + (size_t)b * DIM;
        #pragma unroll 2
        for (int j = 0; j < 16; j++){
            int gid = t + NT*j;
            u64 v[4], vs[4], o[4];
            #pragma unroll
            for (int s = 0; s < 4; s++){
                float re = __ldg(srb + gid + (s << 12));
                float im = __ldg(sib + gid + (s << 12));
                v[s] = pk2(re, im); vs[s] = pk2(im, re);
            }
            mv4(M, v, vs, o);
            #pragma unroll
            for (int s = 0; s < 4; s++){
                float lo, hi; upk2(o[s], lo, hi);
                psi[gid + (s << 12)] = make_float2(lo, hi);
            }
        }
    }
    __syncthreads();

    #pragma unroll 1
    for (int l = 0; l < 3; l++){
        int kstart = (l == 0) ? 1 : 0;
        #pragma unroll 1
        for (int k = kstart; k < 5; k++){
            Mat4 M; loadmat(M, l*7 + k);
            pass2w(psi, M, 12 - 2*k, t);
            __syncthreads();
        }
        {
            Mat4 A, B; loadmat(A, l*7 + 5); loadmat(B, l*7 + 6);
            tilepass(psi, A, B, t);
            __syncthreads();
        }
        if (l < 2){
            permpass(psi, t);
            __syncthreads();
        }
    }

    // measurement: fold final CNOT-ring permutation via o = P(j); signed prob sums
    float zs[NW];
    #pragma unroll
    for (int w = 0; w < NW; w++) zs[w] = 0.f;
    #pragma unroll 8
    for (int j = 0; j < 64; j++){
        int i = t + NT*j;
        float2 a = psi[i];
        float pr = a.x*a.x + a.y*a.y;
        int o = pfwd(i);
        #pragma unroll
        for (int w = 0; w < NW; w++)
            zs[w] += (o & (1 << (13 - w))) ? -pr : pr;
    }
    // warp reduce
    #pragma unroll
    for (int off = 16; off > 0; off >>= 1)
        #pragma unroll
        for (int w = 0; w < NW; w++)
            zs[w] += __shfl_down_sync(0xffffffffu, zs[w], off);
    __syncthreads();                       // all psi reads done; reuse as scratch
    float* red = (float*)psi;
    int lane = t & 31, wid = t >> 5;
    if (lane == 0){
        #pragma unroll
        for (int w = 0; w < NW; w++) red[w*8 + wid] = zs[w];
    }
    __syncthreads();
    if (t == 0){
        float acc = __ldg(hb);
        #pragma unroll
        for (int w = 0; w < NW; w++){
            float f = 0.f;
            #pragma unroll
            for (int r = 0; r < 8; r++) f += red[w*8 + r];
            acc += f * __ldg(hw + w);
        }
        out[b] = acc;
    }
}

// ---------------- launch ----------------

extern "C" void kernel_launch(void* const* d_in, const int* in_sizes, int n_in,
                              void* d_out, int out_size)
{
    const float* sr = (const float*)d_in[0];
    const float* si = (const float*)d_in[1];
    const float* vp = (const float*)d_in[2];
    const float* hw = (const float*)d_in[3];
    const float* hb = (const float*)d_in[4];
    float* out = (float*)d_out;

    cudaFuncSetAttribute(qsim_kernel, cudaFuncAttributeMaxDynamicSharedMemorySize, 131072);

    setup_mats<<<1, 32>>>(vp);

    int B = in_sizes[0] / DIM;
    qsim_kernel<<<B, NT, 131072>>>(sr, si, hw, hb, out);
}